// round 13
// baseline (speedup 1.0000x reference)
#include <cuda_runtime.h>
#include <cuda_fp16.h>
#include <stdint.h>
#include <math.h>

#define BB 4
#define CC 256
#define NN 4096          // H*W
#define MT (BB*NN)       // 16384 tokens
#define BQ 64            // queries per CTA (flash)
#define BKC 32           // keys per chunk (flash)
#define NCH (NN/BKC)     // 128 chunks

// ---------------- device scratch (no allocation) ---------------------------
static __device__ __half g_X [(size_t)MT*CC];              // X+PE, fp16 (B,N,C)
static __device__ __half g_Pt[CC*CC];
static __device__ __half g_Wv[CC*CC];
static __device__ __half g_T [(size_t)MT*CC];              // Q = X@Pt^T (B,N,C)
static __device__ __half g_Vt[(size_t)MT*CC];              // (B, C, N)

// ---------------- PTX helpers (base features only) -------------------------
__device__ __forceinline__ uint32_t smem_u32(const void* p){
  uint32_t a;
  asm("{ .reg .u64 t; cvta.to.shared.u64 t, %1; cvt.u32.u64 %0, t; }" : "=r"(a) : "l"(p));
  return a;
}
__device__ __forceinline__ void cp_async16(uint32_t dst, const void* src){
  asm volatile("cp.async.cg.shared.global [%0], [%1], 16;" :: "r"(dst), "l"(src));
}
__device__ __forceinline__ void cp_commit(){
  asm volatile("cp.async.commit_group;" ::: "memory");
}
__device__ __forceinline__ void cp_wait0(){
  asm volatile("cp.async.wait_group 0;" ::: "memory");
}
__device__ __forceinline__ void cp_wait1(){
  asm volatile("cp.async.wait_group 1;" ::: "memory");
}
__device__ __forceinline__ void cp_wait2(){
  asm volatile("cp.async.wait_group 2;" ::: "memory");
}
__device__ __forceinline__ void ldm4(uint32_t& r0, uint32_t& r1, uint32_t& r2,
                                     uint32_t& r3, uint32_t a){
  asm volatile("ldmatrix.sync.aligned.m8n8.x4.shared.b16 {%0,%1,%2,%3}, [%4];"
   : "=r"(r0), "=r"(r1), "=r"(r2), "=r"(r3) : "r"(a));
}
__device__ __forceinline__ void mma16816(float* d, const uint32_t* a, const uint32_t* b){
  asm volatile("mma.sync.aligned.m16n8k16.row.col.f32.f16.f16.f32 "
   "{%0,%1,%2,%3}, {%4,%5,%6,%7}, {%8,%9}, {%0,%1,%2,%3};"
   : "+f"(d[0]), "+f"(d[1]), "+f"(d[2]), "+f"(d[3])
   : "r"(a[0]), "r"(a[1]), "r"(a[2]), "r"(a[3]), "r"(b[0]), "r"(b[1]));
}
__device__ __forceinline__ uint32_t pack_f2h2(float a, float b){
  __half2 t = __floats2half2_rn(a, b);
  return *(uint32_t*)&t;
}
__device__ __forceinline__ float ex2(float x){
  float r;
  asm("ex2.approx.ftz.f32 %0, %1;" : "=f"(r) : "f"(x));
  return r;
}
// Packed half2 EX2: one MUFU op for two exponentials; returns f16x2 bits.
__device__ __forceinline__ uint32_t ex2_h2(float a, float b, float& s){
  uint32_t h = pack_f2h2(a, b);
  uint32_t r;
  asm("ex2.approx.f16x2 %0, %1;" : "=r"(r) : "r"(h));
  __half2 p = *(__half2*)&r;
  s += __half2float(p.x) + __half2float(p.y);
  return r;
}

// ---------------- kernel: x + PE -> fp16 (B,N,C) ----------------------------
__global__ void pe_transpose_kernel(const float* __restrict__ x) {
    __shared__ float tile[32][33];
    int b  = blockIdx.z;
    int c0 = blockIdx.y * 32, n0 = blockIdx.x * 32;
    int tx = threadIdx.x, ty = threadIdx.y;
    tile[ty][tx] = x[((size_t)(b*CC + c0 + ty))*NN + n0 + tx];
    __syncthreads();
    int c = c0 + tx, n = n0 + ty;
    int h = n >> 6, w = n & 63;
    int pos, cc;
    if (c < 128) { pos = w; cc = c; } else { pos = h; cc = c - 128; }
    int j = cc & 63;
    float inv = expf(-0.14391156831212787f * (float)j);
    float arg = (float)pos * inv;
    float pe = (cc >= 64) ? cosf(arg) : sinf(arg);
    g_X[((size_t)(b*NN + n))*CC + c] = __float2half_rn(tile[tx][ty] + pe);
}

// ---------------- kernel: Pt[e,c] = scale * sum_d Wq[d,c]*Wk[d,e] ----------
__global__ void pt_kernel(const float* __restrict__ wq, const float* __restrict__ wk){
  int e = blockIdx.x, c = threadIdx.x;
  float acc = 0.f;
  for (int d = 0; d < CC; d++)
    acc += wq[d*CC + c] * wk[d*CC + e];
  g_Pt[e*CC + c] = __float2half_rn(acc * 0.09016844004f);  // 0.0625*log2(e)
}

__global__ void cvtW_kernel(const float* __restrict__ wv){
  int i = blockIdx.x*256 + threadIdx.x;
  g_Wv[i] = __float2half_rn(wv[i]);
}

// ---------------- mma.sync GEMM (NT), fp16 operands ------------------------
template<int MODE>
__global__ void __launch_bounds__(256, 1)
gemm_mma(const __half* __restrict__ Am, const __half* __restrict__ Bm,
         __half* __restrict__ O1, int lda, int ldb, int K)
{
  extern __shared__ char sm[];
  const int tid  = threadIdx.x;
  const int lane = tid & 31, wid = tid >> 5;
  const int wm   = (wid >> 2) * 64;
  const int wn   = (wid & 3) * 32;

  const int m0 = blockIdx.y * 128, n0 = blockIdx.x * 128;
  const __half* aP = Am + (size_t)m0 * lda;
  const __half* bP = Bm + (size_t)n0 * ldb;

  const uint32_t sb = smem_u32(sm);

  auto load_chunk = [&](int ck, int stage){
    const int kt = ck << 6;
    const uint32_t base = sb + stage * 32768;
    #pragma unroll
    for (int u = 0; u < 4; u++){
      int idx = u*256 + tid;
      int r = idx >> 3, c = idx & 7;
      uint32_t dst = base + r*128 + ((c ^ (r & 7)) << 4);
      cp_async16(dst, aP + (size_t)r*lda + kt + c*8);
    }
    #pragma unroll
    for (int u = 0; u < 4; u++){
      int idx = u*256 + tid;
      int r = idx >> 3, c = idx & 7;
      uint32_t dst = base + 16384 + r*128 + ((c ^ (r & 7)) << 4);
      cp_async16(dst, bP + (size_t)r*ldb + kt + c*8);
    }
    cp_commit();
  };

  float acc[4][4][4] = {};
  const int nchunk = K >> 6;
  load_chunk(0, 0);

  for (int ck = 0; ck < nchunk; ck++){
    const int st = ck & 1;
    if (ck + 1 < nchunk){ load_chunk(ck + 1, st ^ 1); cp_wait1(); }
    else                { cp_wait0(); }
    __syncthreads();

    const uint32_t Abase = sb + st * 32768;
    const uint32_t Bbase = Abase + 16384;
    const int rsel = lane & 15;
    const int csel = lane >> 4;

    #pragma unroll
    for (int ks = 0; ks < 4; ks++){
      const int cA = ks*2 + csel;
      uint32_t ahf[4][4];
      #pragma unroll
      for (int mt = 0; mt < 4; mt++){
        int row = wm + mt*16 + rsel;
        uint32_t ad = Abase + row*128 + ((cA ^ (row & 7)) << 4);
        ldm4(ahf[mt][0], ahf[mt][1], ahf[mt][2], ahf[mt][3], ad);
      }
      uint32_t bhf[4][2];
      #pragma unroll
      for (int g = 0; g < 2; g++){
        int row = wn + g*16 + rsel;
        uint32_t bd = Bbase + row*128 + ((cA ^ (row & 7)) << 4);
        uint32_t r0, r1, r2, r3;
        ldm4(r0, r1, r2, r3, bd);
        bhf[g*2][0] = r0; bhf[g*2][1] = r2;
        bhf[g*2+1][0] = r1; bhf[g*2+1][1] = r3;
      }
      #pragma unroll
      for (int mt = 0; mt < 4; mt++)
        #pragma unroll
        for (int nt = 0; nt < 4; nt++)
          mma16816(acc[mt][nt], ahf[mt], bhf[nt]);
    }
    __syncthreads();
  }

  if (MODE == 0){
    #pragma unroll
    for (int mt = 0; mt < 4; mt++)
      #pragma unroll
      for (int nt = 0; nt < 4; nt++){
        int r = m0 + wm + mt*16 + (lane >> 2);
        int c = n0 + wn + nt*8  + (lane & 3)*2;
        *(__half2*)(O1 + (size_t)r*CC + c) =
            __floats2half2_rn(acc[mt][nt][0], acc[mt][nt][1]);
        *(__half2*)(O1 + (size_t)(r+8)*CC + c) =
            __floats2half2_rn(acc[mt][nt][2], acc[mt][nt][3]);
      }
  } else {
    float* stg = (float*)sm;             // 128 x 132 floats = 67584 B
    #pragma unroll
    for (int mt = 0; mt < 4; mt++)
      #pragma unroll
      for (int nt = 0; nt < 4; nt++){
        int r = wm + mt*16 + (lane >> 2);
        int c = wn + nt*8  + (lane & 3)*2;
        stg[r*132 + c]     = acc[mt][nt][0];
        stg[r*132 + c + 1] = acc[mt][nt][1];
        stg[(r+8)*132 + c]     = acc[mt][nt][2];
        stg[(r+8)*132 + c + 1] = acc[mt][nt][3];
      }
    __syncthreads();
    int b = m0 / NN, tok0 = m0 % NN;
    int cl = tid >> 1, seg = tid & 1;
    size_t base = (size_t)(b*CC + n0 + cl)*NN + tok0 + seg*64;
    #pragma unroll
    for (int i = 0; i < 64; i += 2){
      __half2 hv = __floats2half2_rn(stg[(seg*64 + i)*132 + cl],
                                     stg[(seg*64 + i + 1)*132 + cl]);
      *(__half2*)(O1 + base + i) = hv;
    }
  }
}

// ---------------- fused flash attention: 2 CTAs/SM -------------------------
// BQ=64, BKC=32, 128 threads (4 warps). Warp owns 16 rows x all keys x all
// dims; register-resident P; warp-local softmax. 2 CTAs per SM overlap each
// other's softmax/sync bubbles with HMMA work.
// smem/CTA: Q 32K | K ring 2x16K | V ring 2x20K (80B pitch) = 104 KB
#define SM_Q    0
#define SM_KR   32768
#define SM_VR   65536
#define SM_FLASH 106496

__global__ void __launch_bounds__(128, 2)
flash_kernel(float* __restrict__ out)
{
  extern __shared__ char sm[];
  const uint32_t sb = smem_u32(sm);
  const int tid = threadIdx.x, lane = tid & 31, wid = tid >> 5;
  const int b  = blockIdx.y;
  const int q0 = blockIdx.x * BQ;
  const int qs = wid * 16;
  const int rsel = lane & 15, csel = lane >> 4;

  auto load_K = [&](int j){
    int k0 = j * BKC;
    uint32_t base = sb + SM_KR + (j & 1)*16384;
    #pragma unroll
    for (int u = 0; u < 8; u++){
      int idx = u*128 + tid;            // 32 rows x 32 chunks
      int r = idx >> 5, c = idx & 31;
      uint32_t dst = base + r*512 + ((c ^ (r & 7)) << 4);
      cp_async16(dst, g_X + ((size_t)(b*NN + k0 + r))*CC + c*8);
    }
    cp_commit();
  };
  auto load_V = [&](int j){
    int k0 = j * BKC;
    uint32_t base = sb + SM_VR + (j & 1)*20480;
    #pragma unroll
    for (int u = 0; u < 8; u++){
      int idx = u*128 + tid;            // 256 rows x 4 chunks, 80B pitch
      int r = idx >> 2, c = idx & 3;
      uint32_t dst = base + r*80 + c*16;
      cp_async16(dst, g_Vt + ((size_t)(b*CC + r))*NN + k0 + c*8);
    }
    cp_commit();
  };

  // prologue: [Q], [K0], [V0], [K1]
  #pragma unroll
  for (int u = 0; u < 16; u++){
    int idx = u*128 + tid;              // 64 rows x 32 chunks
    int r = idx >> 5, c = idx & 31;
    uint32_t dst = sb + SM_Q + r*512 + ((c ^ (r & 7)) << 4);
    cp_async16(dst, g_T + ((size_t)(b*NN + q0 + r))*CC + c*8);
  }
  cp_commit();
  load_K(0);
  load_V(0);
  load_K(1);

  float m0r = -1e30f, m1r = -1e30f, l0r = 0.f, l1r = 0.f;
  float accY[32][4] = {};
  float accS[4][4] = {};

  cp_wait2();                 // Q, K0 ready
  __syncthreads();

  // ---- S_0 (16 rows x 32 keys per warp) ----
  {
    const uint32_t Kbase = sb + SM_KR;
    #pragma unroll 4
    for (int ks = 0; ks < 16; ks++){
      const int cA = ks*2 + csel;
      int qrow = qs + rsel;
      uint32_t ad = sb + SM_Q + qrow*512 + ((cA ^ (qrow & 7)) << 4);
      uint32_t qh[4];
      ldm4(qh[0], qh[1], qh[2], qh[3], ad);
      #pragma unroll
      for (int g = 0; g < 2; g++){
        int krow = g*16 + rsel;
        uint32_t bd = Kbase + krow*512 + ((cA ^ (krow & 7)) << 4);
        uint32_t r0, r1, r2, r3;
        ldm4(r0, r1, r2, r3, bd);
        uint32_t be[2] = {r0, r2}, bo[2] = {r1, r3};
        mma16816(accS[2*g],   qh, be);
        mma16816(accS[2*g+1], qh, bo);
      }
    }
  }

  for (int j = 0; j < NCH; j++){
    // ---- softmax_j (log2 domain, warp-local) -------------------------------
    float mx0 = -1e30f, mx1 = -1e30f;
    #pragma unroll
    for (int nt = 0; nt < 4; nt++){
      mx0 = fmaxf(mx0, fmaxf(accS[nt][0], accS[nt][1]));
      mx1 = fmaxf(mx1, fmaxf(accS[nt][2], accS[nt][3]));
    }
    mx0 = fmaxf(mx0, __shfl_xor_sync(0xffffffffu, mx0, 1));
    mx0 = fmaxf(mx0, __shfl_xor_sync(0xffffffffu, mx0, 2));
    mx1 = fmaxf(mx1, __shfl_xor_sync(0xffffffffu, mx1, 1));
    mx1 = fmaxf(mx1, __shfl_xor_sync(0xffffffffu, mx1, 2));
    float mn0 = fmaxf(m0r, mx0), mn1 = fmaxf(m1r, mx1);
    float f0 = ex2(m0r - mn0), f1 = ex2(m1r - mn1);
    m0r = mn0; m1r = mn1;

    uint32_t pp[4][2];
    float s0 = 0.f, s1 = 0.f;
    #pragma unroll
    for (int nt = 0; nt < 4; nt++){
      pp[nt][0] = ex2_h2(accS[nt][0] - mn0, accS[nt][1] - mn0, s0);
      pp[nt][1] = ex2_h2(accS[nt][2] - mn1, accS[nt][3] - mn1, s1);
    }
    s0 += __shfl_xor_sync(0xffffffffu, s0, 1);
    s0 += __shfl_xor_sync(0xffffffffu, s0, 2);
    s1 += __shfl_xor_sync(0xffffffffu, s1, 1);
    s1 += __shfl_xor_sync(0xffffffffu, s1, 2);
    l0r = l0r*f0 + s0;
    l1r = l1r*f1 + s1;

    // ---- rotate ring: issue loads, rescale hides latency --------------------
    __syncthreads();                      // all warps done with K_j, V_{j-1}
    load_V(j + 1 < NCH ? j + 1 : NCH - 1);
    load_K(j + 2 < NCH ? j + 2 : NCH - 1);

    if (!__all_sync(0xffffffffu, (f0 == 1.0f) && (f1 == 1.0f))){
      #pragma unroll
      for (int nt = 0; nt < 32; nt++){
        accY[nt][0] *= f0; accY[nt][1] *= f0;
        accY[nt][2] *= f1; accY[nt][3] *= f1;
      }
    }

    cp_wait2();                           // V_j, K_{j+1} ready
    __syncthreads();

    const uint32_t Vbase = sb + SM_VR + (j & 1)*20480;
    const uint32_t Kbase = sb + SM_KR + ((j + 1) & 1)*16384;
    const bool do_s = (j + 1 < NCH);

    #pragma unroll
    for (int nt = 0; nt < 4; nt++){
      accS[nt][0] = 0.f; accS[nt][1] = 0.f; accS[nt][2] = 0.f; accS[nt][3] = 0.f;
    }

    // ---- interleaved: PV_j (16 rows x 256 dims) + S_{j+1} -------------------
    #pragma unroll
    for (int u = 0; u < 2; u++){
      // PV k-slice u (keys u*16..u*16+15)
      {
        uint32_t a_p[4] = {pp[2*u][0], pp[2*u][1], pp[2*u+1][0], pp[2*u+1][1]};
        const int cV = u*2 + csel;
        #pragma unroll
        for (int g = 0; g < 16; g++){
          int vrow = g*16 + rsel;
          uint32_t bd = Vbase + vrow*80 + (cV << 4);
          uint32_t r0, r1, r2, r3;
          ldm4(r0, r1, r2, r3, bd);
          uint32_t be[2] = {r0, r2}, bo[2] = {r1, r3};
          mma16816(accY[2*g],   a_p, be);
          mma16816(accY[2*g+1], a_p, bo);
        }
      }
      // S half (8 k-slices)
      if (do_s){
        #pragma unroll
        for (int s = 0; s < 8; s++){
          const int cA = (u*8 + s)*2 + csel;
          int qrow = qs + rsel;
          uint32_t ad = sb + SM_Q + qrow*512 + ((cA ^ (qrow & 7)) << 4);
          uint32_t qh[4];
          ldm4(qh[0], qh[1], qh[2], qh[3], ad);
          #pragma unroll
          for (int g = 0; g < 2; g++){
            int krow = g*16 + rsel;
            uint32_t bd = Kbase + krow*512 + ((cA ^ (krow & 7)) << 4);
            uint32_t r0, r1, r2, r3;
            ldm4(r0, r1, r2, r3, bd);
            uint32_t be[2] = {r0, r2}, bo[2] = {r1, r3};
            mma16816(accS[2*g],   qh, be);
            mma16816(accS[2*g+1], qh, bo);
          }
        }
      }
    }
  }

  cp_wait0();
  __syncthreads();

  // ---- epilogue: normalize, stage, write (B,C,H,W) --------------------------
  float* stg = (float*)sm;                     // [64 tokens][260]
  {
    float inv0 = 1.0f / l0r, inv1 = 1.0f / l1r;
    int rA = qs + (lane >> 2), rB = rA + 8;
    #pragma unroll
    for (int nt = 0; nt < 32; nt++){
      int c = nt*8 + (lane & 3)*2;
      stg[rA*260 + c]     = accY[nt][0]*inv0;
      stg[rA*260 + c + 1] = accY[nt][1]*inv0;
      stg[rB*260 + c]     = accY[nt][2]*inv1;
      stg[rB*260 + c + 1] = accY[nt][3]*inv1;
    }
  }
  __syncthreads();
  #pragma unroll
  for (int it = 0; it < 8; it++){
    int dim = it*32 + (tid >> 2);
    int seg = (tid & 3) * 16;
    float* op = out + (size_t)(b*CC + dim)*NN + q0 + seg;
    #pragma unroll
    for (int k = 0; k < 16; k += 4){
      float4 v;
      v.x = stg[(seg + k + 0)*260 + dim];
      v.y = stg[(seg + k + 1)*260 + dim];
      v.z = stg[(seg + k + 2)*260 + dim];
      v.w = stg[(seg + k + 3)*260 + dim];
      *(float4*)(op + k) = v;
    }
  }
}

// ---------------- launch ----------------------------------------------------
extern "C" void kernel_launch(void* const* d_in, const int* in_sizes, int n_in,
                              void* d_out, int out_size)
{
    const float* x  = (const float*)d_in[0];
    const float* wq = (const float*)d_in[1];
    const float* wk = (const float*)d_in[2];
    const float* wv = (const float*)d_in[3];
    float* out = (float*)d_out;

    __half *X, *Pt, *Wv, *T, *Vt;
    cudaGetSymbolAddress((void**)&X,  g_X);
    cudaGetSymbolAddress((void**)&Pt, g_Pt);  cudaGetSymbolAddress((void**)&Wv, g_Wv);
    cudaGetSymbolAddress((void**)&T,  g_T);   cudaGetSymbolAddress((void**)&Vt, g_Vt);

    const int SMEM_P = 69632;
    cudaFuncSetAttribute((const void*)gemm_mma<0>,
        cudaFuncAttributeMaxDynamicSharedMemorySize, SMEM_P);
    cudaFuncSetAttribute((const void*)gemm_mma<1>,
        cudaFuncAttributeMaxDynamicSharedMemorySize, SMEM_P);
    cudaFuncSetAttribute((const void*)flash_kernel,
        cudaFuncAttributeMaxDynamicSharedMemorySize, SM_FLASH);

    // 1) X = x + PE, fp16, (B,N,C)
    pe_transpose_kernel<<<dim3(NN/32, CC/32, BB), dim3(32,32)>>>(x);

    // 2) Pt = (0.0625*log2e) * Wq^T Wk (fp16), Wv fp16
    pt_kernel<<<CC, CC>>>(wq, wk);
    cvtW_kernel<<<CC*CC/256, 256>>>(wv);

    // 3) T = X @ Pt^T -> fp16 row-major
    gemm_mma<0><<<dim3(CC/128, MT/128, 1), 256, SMEM_P>>>(X, Pt, T, CC, CC, CC);

    // 4) Vt = (X @ Wv^T)^T -> fp16 (B,C,N)
    gemm_mma<1><<<dim3(CC/128, MT/128, 1), 256, SMEM_P>>>(X, Wv, Vt, CC, CC, CC);

    // 5) fused flash attention (2 CTAs/SM) -> writes out (B,C,H,W) directly
    flash_kernel<<<dim3(NN/BQ, BB), 128, SM_FLASH>>>(out);
}

// round 14
// speedup vs baseline: 1.0793x; 1.0793x over previous
#include <cuda_runtime.h>
#include <cuda_fp16.h>
#include <stdint.h>
#include <math.h>

#define BB 4
#define CC 256
#define NN 4096          // H*W
#define MT (BB*NN)       // 16384 tokens
#define BQ 128           // queries per CTA (flash)
#define BKC 64           // keys per chunk (flash)
#define NCH (NN/BKC)     // 64 chunks

// ---------------- device scratch (no allocation) ---------------------------
static __device__ __half g_X [(size_t)MT*CC];              // X+PE, fp16 (B,N,C)
static __device__ __half g_Pt[CC*CC];
static __device__ __half g_Wv[CC*CC];
static __device__ __half g_T [(size_t)MT*CC];              // Q = X@Pt^T (B,N,C)
static __device__ __half g_Vt[(size_t)MT*CC];              // (B, C, N)

// ---------------- PTX helpers (base features only) -------------------------
__device__ __forceinline__ uint32_t smem_u32(const void* p){
  uint32_t a;
  asm("{ .reg .u64 t; cvta.to.shared.u64 t, %1; cvt.u32.u64 %0, t; }" : "=r"(a) : "l"(p));
  return a;
}
__device__ __forceinline__ void cp_async16(uint32_t dst, const void* src){
  asm volatile("cp.async.cg.shared.global [%0], [%1], 16;" :: "r"(dst), "l"(src));
}
__device__ __forceinline__ void cp_commit(){
  asm volatile("cp.async.commit_group;" ::: "memory");
}
__device__ __forceinline__ void cp_wait0(){
  asm volatile("cp.async.wait_group 0;" ::: "memory");
}
__device__ __forceinline__ void cp_wait1(){
  asm volatile("cp.async.wait_group 1;" ::: "memory");
}
__device__ __forceinline__ void cp_wait2(){
  asm volatile("cp.async.wait_group 2;" ::: "memory");
}
__device__ __forceinline__ void ldm4(uint32_t& r0, uint32_t& r1, uint32_t& r2,
                                     uint32_t& r3, uint32_t a){
  asm volatile("ldmatrix.sync.aligned.m8n8.x4.shared.b16 {%0,%1,%2,%3}, [%4];"
   : "=r"(r0), "=r"(r1), "=r"(r2), "=r"(r3) : "r"(a));
}
__device__ __forceinline__ void mma16816(float* d, const uint32_t* a, const uint32_t* b){
  asm volatile("mma.sync.aligned.m16n8k16.row.col.f32.f16.f16.f32 "
   "{%0,%1,%2,%3}, {%4,%5,%6,%7}, {%8,%9}, {%0,%1,%2,%3};"
   : "+f"(d[0]), "+f"(d[1]), "+f"(d[2]), "+f"(d[3])
   : "r"(a[0]), "r"(a[1]), "r"(a[2]), "r"(a[3]), "r"(b[0]), "r"(b[1]));
}
__device__ __forceinline__ uint32_t pack_f2h2(float a, float b){
  __half2 t = __floats2half2_rn(a, b);
  return *(uint32_t*)&t;
}
__device__ __forceinline__ float ex2(float x){
  float r;
  asm("ex2.approx.ftz.f32 %0, %1;" : "=f"(r) : "f"(x));
  return r;
}
// Packed half2 EX2: one MUFU op for two exponentials; returns f16x2 bits.
__device__ __forceinline__ uint32_t ex2_h2(float a, float b, float& s){
  uint32_t h = pack_f2h2(a, b);
  uint32_t r;
  asm("ex2.approx.f16x2 %0, %1;" : "=r"(r) : "r"(h));
  __half2 p = *(__half2*)&r;
  s += __half2float(p.x) + __half2float(p.y);
  return r;
}
__device__ __forceinline__ void bar_pair(int id){
  asm volatile("bar.sync %0, 64;" :: "r"(id) : "memory");
}

// ---------------- kernel: x + PE -> fp16 (B,N,C) ----------------------------
__global__ void pe_transpose_kernel(const float* __restrict__ x) {
    __shared__ float tile[32][33];
    int b  = blockIdx.z;
    int c0 = blockIdx.y * 32, n0 = blockIdx.x * 32;
    int tx = threadIdx.x, ty = threadIdx.y;
    tile[ty][tx] = x[((size_t)(b*CC + c0 + ty))*NN + n0 + tx];
    __syncthreads();
    int c = c0 + tx, n = n0 + ty;
    int h = n >> 6, w = n & 63;
    int pos, cc;
    if (c < 128) { pos = w; cc = c; } else { pos = h; cc = c - 128; }
    int j = cc & 63;
    float inv = expf(-0.14391156831212787f * (float)j);
    float arg = (float)pos * inv;
    float pe = (cc >= 64) ? cosf(arg) : sinf(arg);
    g_X[((size_t)(b*NN + n))*CC + c] = __float2half_rn(tile[tx][ty] + pe);
}

// ---------------- merged: Pt = scale*Wq^T Wk  |  Wv -> fp16 ------------------
__global__ void prep_kernel(const float* __restrict__ wq,
                            const float* __restrict__ wk,
                            const float* __restrict__ wv){
  if (blockIdx.x < CC){
    int e = blockIdx.x, c = threadIdx.x;
    float acc = 0.f;
    for (int d = 0; d < CC; d++)
      acc += wq[d*CC + c] * wk[d*CC + e];
    g_Pt[e*CC + c] = __float2half_rn(acc * 0.09016844004f);  // 0.0625*log2(e)
  } else {
    int i = (blockIdx.x - CC)*256 + threadIdx.x;
    g_Wv[i] = __float2half_rn(wv[i]);
  }
}

// ---------------- mma.sync GEMM (NT), fp16 operands ------------------------
template<int MODE>
__global__ void __launch_bounds__(256, 1)
gemm_mma(const __half* __restrict__ Am, const __half* __restrict__ Bm,
         __half* __restrict__ O1, int lda, int ldb, int K)
{
  extern __shared__ char sm[];
  const int tid  = threadIdx.x;
  const int lane = tid & 31, wid = tid >> 5;
  const int wm   = (wid >> 2) * 64;
  const int wn   = (wid & 3) * 32;

  const int m0 = blockIdx.y * 128, n0 = blockIdx.x * 128;
  const __half* aP = Am + (size_t)m0 * lda;
  const __half* bP = Bm + (size_t)n0 * ldb;

  const uint32_t sb = smem_u32(sm);

  auto load_chunk = [&](int ck, int stage){
    const int kt = ck << 6;
    const uint32_t base = sb + stage * 32768;
    #pragma unroll
    for (int u = 0; u < 4; u++){
      int idx = u*256 + tid;
      int r = idx >> 3, c = idx & 7;
      uint32_t dst = base + r*128 + ((c ^ (r & 7)) << 4);
      cp_async16(dst, aP + (size_t)r*lda + kt + c*8);
    }
    #pragma unroll
    for (int u = 0; u < 4; u++){
      int idx = u*256 + tid;
      int r = idx >> 3, c = idx & 7;
      uint32_t dst = base + 16384 + r*128 + ((c ^ (r & 7)) << 4);
      cp_async16(dst, bP + (size_t)r*ldb + kt + c*8);
    }
    cp_commit();
  };

  float acc[4][4][4] = {};
  const int nchunk = K >> 6;
  load_chunk(0, 0);

  for (int ck = 0; ck < nchunk; ck++){
    const int st = ck & 1;
    if (ck + 1 < nchunk){ load_chunk(ck + 1, st ^ 1); cp_wait1(); }
    else                { cp_wait0(); }
    __syncthreads();

    const uint32_t Abase = sb + st * 32768;
    const uint32_t Bbase = Abase + 16384;
    const int rsel = lane & 15;
    const int csel = lane >> 4;

    #pragma unroll
    for (int ks = 0; ks < 4; ks++){
      const int cA = ks*2 + csel;
      uint32_t ahf[4][4];
      #pragma unroll
      for (int mt = 0; mt < 4; mt++){
        int row = wm + mt*16 + rsel;
        uint32_t ad = Abase + row*128 + ((cA ^ (row & 7)) << 4);
        ldm4(ahf[mt][0], ahf[mt][1], ahf[mt][2], ahf[mt][3], ad);
      }
      uint32_t bhf[4][2];
      #pragma unroll
      for (int g = 0; g < 2; g++){
        int row = wn + g*16 + rsel;
        uint32_t bd = Bbase + row*128 + ((cA ^ (row & 7)) << 4);
        uint32_t r0, r1, r2, r3;
        ldm4(r0, r1, r2, r3, bd);
        bhf[g*2][0] = r0; bhf[g*2][1] = r2;
        bhf[g*2+1][0] = r1; bhf[g*2+1][1] = r3;
      }
      #pragma unroll
      for (int mt = 0; mt < 4; mt++)
        #pragma unroll
        for (int nt = 0; nt < 4; nt++)
          mma16816(acc[mt][nt], ahf[mt], bhf[nt]);
    }
    __syncthreads();
  }

  if (MODE == 0){
    #pragma unroll
    for (int mt = 0; mt < 4; mt++)
      #pragma unroll
      for (int nt = 0; nt < 4; nt++){
        int r = m0 + wm + mt*16 + (lane >> 2);
        int c = n0 + wn + nt*8  + (lane & 3)*2;
        *(__half2*)(O1 + (size_t)r*CC + c) =
            __floats2half2_rn(acc[mt][nt][0], acc[mt][nt][1]);
        *(__half2*)(O1 + (size_t)(r+8)*CC + c) =
            __floats2half2_rn(acc[mt][nt][2], acc[mt][nt][3]);
      }
  } else {
    float* stg = (float*)sm;             // 128 x 132 floats = 67584 B
    #pragma unroll
    for (int mt = 0; mt < 4; mt++)
      #pragma unroll
      for (int nt = 0; nt < 4; nt++){
        int r = wm + mt*16 + (lane >> 2);
        int c = wn + nt*8  + (lane & 3)*2;
        stg[r*132 + c]     = acc[mt][nt][0];
        stg[r*132 + c + 1] = acc[mt][nt][1];
        stg[(r+8)*132 + c]     = acc[mt][nt][2];
        stg[(r+8)*132 + c + 1] = acc[mt][nt][3];
      }
    __syncthreads();
    int b = m0 / NN, tok0 = m0 % NN;
    int cl = tid >> 1, seg = tid & 1;
    size_t base = (size_t)(b*CC + n0 + cl)*NN + tok0 + seg*64;
    #pragma unroll
    for (int i = 0; i < 64; i += 2){
      __half2 hv = __floats2half2_rn(stg[(seg*64 + i)*132 + cl],
                                     stg[(seg*64 + i + 1)*132 + cl]);
      *(__half2*)(O1 + base + i) = hv;
    }
  }
}

// ---------------- fused flash attention -------------------------------------
// BQ=128 q/CTA, 8 warps. S: warp = 16 rows x 64 keys (warp-local softmax).
// PV: warp = 32 rows x 128 dims; P via 16KB smem (pair-local exchange).
// ONE block barrier per chunk; P/f handoff uses a 64-thread pair barrier.
// smem: Q 64K | K ring 2x32K | V ring 2x32K | P 16K | f/l 512B
#define SM_Q    0
#define SM_KR   65536
#define SM_VR   131072
#define SM_P    196608
#define SM_F    212992
#define SM_FLASH 213504

__global__ void __launch_bounds__(256, 1)
flash_kernel(float* __restrict__ out)
{
  extern __shared__ char sm[];
  const uint32_t sb = smem_u32(sm);
  float* fbuf = (float*)(sm + SM_F);    // per-row f (per chunk) then l (final)
  const int tid = threadIdx.x, lane = tid & 31, wid = tid >> 5;
  const int b  = blockIdx.y;
  const int q0 = blockIdx.x * BQ;
  const int qs = wid * 16;              // softmax/S row base
  const int mg = wid >> 1, dg = wid & 1;
  const int pvm = mg * 32;              // PV row base
  const int pvd = dg * 128;             // PV dim base
  const int pbar = 1 + mg;              // named barrier id for warp pair
  const int rsel = lane & 15, csel = lane >> 4;

  auto load_K = [&](int j){
    int k0 = j * BKC;
    uint32_t base = sb + SM_KR + (j & 1)*32768;
    #pragma unroll
    for (int u = 0; u < 8; u++){
      int idx = u*256 + tid;            // 64 rows x 32 chunks
      int r = idx >> 5, c = idx & 31;
      uint32_t dst = base + r*512 + ((c ^ (r & 7)) << 4);
      cp_async16(dst, g_X + ((size_t)(b*NN + k0 + r))*CC + c*8);
    }
    cp_commit();
  };
  auto load_V = [&](int j){
    int k0 = j * BKC;
    uint32_t base = sb + SM_VR + (j & 1)*32768;
    #pragma unroll
    for (int u = 0; u < 8; u++){
      int idx = u*256 + tid;            // 256 rows x 8 chunks
      int r = idx >> 3, c = idx & 7;
      uint32_t dst = base + r*128 + ((c ^ (r & 7)) << 4);
      cp_async16(dst, g_Vt + ((size_t)(b*CC + r))*NN + k0 + c*8);
    }
    cp_commit();
  };

  // prologue: [Q], [K0], [V0], [K1]
  #pragma unroll
  for (int u = 0; u < 16; u++){
    int idx = u*256 + tid;              // 128 rows x 32 chunks
    int r = idx >> 5, c = idx & 31;
    uint32_t dst = sb + SM_Q + r*512 + ((c ^ (r & 7)) << 4);
    cp_async16(dst, g_T + ((size_t)(b*NN + q0 + r))*CC + c*8);
  }
  cp_commit();
  load_K(0);
  load_V(0);
  load_K(1);

  float m0r = -1e30f, m1r = -1e30f, l0r = 0.f, l1r = 0.f;
  float accY[2][16][4] = {};
  float accS[8][4] = {};

  cp_wait2();                 // Q, K0 ready (pending V0, K1)
  __syncthreads();

  // ---- S_0 ----
  {
    const uint32_t Kbase = sb + SM_KR;
    #pragma unroll 4
    for (int ks = 0; ks < 16; ks++){
      const int cA = ks*2 + csel;
      int qrow = qs + rsel;
      uint32_t ad = sb + SM_Q + qrow*512 + ((cA ^ (qrow & 7)) << 4);
      uint32_t qh[4];
      ldm4(qh[0], qh[1], qh[2], qh[3], ad);
      #pragma unroll
      for (int g = 0; g < 4; g++){
        int krow = g*16 + rsel;
        uint32_t bd = Kbase + krow*512 + ((cA ^ (krow & 7)) << 4);
        uint32_t r0, r1, r2, r3;
        ldm4(r0, r1, r2, r3, bd);
        uint32_t be[2] = {r0, r2}, bo[2] = {r1, r3};
        mma16816(accS[2*g],   qh, be);
        mma16816(accS[2*g+1], qh, bo);
      }
    }
  }

  for (int j = 0; j < NCH; j++){
    // ---- softmax_j (log2 domain, warp-local) --------------------------------
    float mx0 = -1e30f, mx1 = -1e30f;
    #pragma unroll
    for (int nt = 0; nt < 8; nt++){
      mx0 = fmaxf(mx0, fmaxf(accS[nt][0], accS[nt][1]));
      mx1 = fmaxf(mx1, fmaxf(accS[nt][2], accS[nt][3]));
    }
    mx0 = fmaxf(mx0, __shfl_xor_sync(0xffffffffu, mx0, 1));
    mx0 = fmaxf(mx0, __shfl_xor_sync(0xffffffffu, mx0, 2));
    mx1 = fmaxf(mx1, __shfl_xor_sync(0xffffffffu, mx1, 1));
    mx1 = fmaxf(mx1, __shfl_xor_sync(0xffffffffu, mx1, 2));
    float mn0 = fmaxf(m0r, mx0), mn1 = fmaxf(m1r, mx1);
    float f0 = ex2(m0r - mn0), f1 = ex2(m1r - mn1);
    m0r = mn0; m1r = mn1;

    uint32_t pp[8][2];
    float s0 = 0.f, s1 = 0.f;
    #pragma unroll
    for (int nt = 0; nt < 8; nt++){
      pp[nt][0] = ex2_h2(accS[nt][0] - mn0, accS[nt][1] - mn0, s0);
      pp[nt][1] = ex2_h2(accS[nt][2] - mn1, accS[nt][3] - mn1, s1);
    }
    s0 += __shfl_xor_sync(0xffffffffu, s0, 1);
    s0 += __shfl_xor_sync(0xffffffffu, s0, 2);
    s1 += __shfl_xor_sync(0xffffffffu, s1, 1);
    s1 += __shfl_xor_sync(0xffffffffu, s1, 2);
    l0r = l0r*f0 + s0;
    l1r = l1r*f1 + s1;

    // ---- single block barrier per chunk -------------------------------------
    cp_wait0();               // V_j, K_{j+1} landed (issued last iteration)
    __syncthreads();          // K_j/V_{j-1}/P_{j-1}/fbuf consumed; V_j,K_{j+1} visible

    // prefetch next (slots provably free: their consumers ran before barrier)
    load_V(j + 1 < NCH ? j + 1 : NCH - 1);
    load_K(j + 2 < NCH ? j + 2 : NCH - 1);

    // ---- publish P_j + f_j (pair-local consumers) ----------------------------
    {
      int rA = qs + (lane >> 2), rB = rA + 8;
      #pragma unroll
      for (int nt = 0; nt < 8; nt++){
        uint32_t wi = (lane & 3) * 4;
        uint32_t oA = SM_P + rA*128 + (((uint32_t)(nt ^ (rA & 7))) << 4) + wi;
        uint32_t oB = SM_P + rB*128 + (((uint32_t)(nt ^ (rB & 7))) << 4) + wi;
        *(uint32_t*)(sm + oA) = pp[nt][0];
        *(uint32_t*)(sm + oB) = pp[nt][1];
      }
      if ((lane & 3) == 0){
        fbuf[rA] = f0;
        fbuf[rB] = f1;
      }
    }
    bar_pair(pbar);           // P rows [pvm,pvm+32) + f visible within pair

    // ---- rescale accY (rows pvm..pvm+31) ------------------------------------
    {
      float fA0 = fbuf[pvm + (lane >> 2)];
      float fB0 = fbuf[pvm + 8 + (lane >> 2)];
      float fA1 = fbuf[pvm + 16 + (lane >> 2)];
      float fB1 = fbuf[pvm + 24 + (lane >> 2)];
      bool need = (fA0 != 1.f) || (fB0 != 1.f) || (fA1 != 1.f) || (fB1 != 1.f);
      if (__any_sync(0xffffffffu, need)){
        #pragma unroll
        for (int nt = 0; nt < 16; nt++){
          accY[0][nt][0] *= fA0; accY[0][nt][1] *= fA0;
          accY[0][nt][2] *= fB0; accY[0][nt][3] *= fB0;
          accY[1][nt][0] *= fA1; accY[1][nt][1] *= fA1;
          accY[1][nt][2] *= fB1; accY[1][nt][3] *= fB1;
        }
      }
    }

    const uint32_t Vbase = sb + SM_VR + (j & 1)*32768;
    const uint32_t Kbase = sb + SM_KR + ((j + 1) & 1)*32768;
    const bool do_s = (j + 1 < NCH);

    #pragma unroll
    for (int nt = 0; nt < 8; nt++){
      accS[nt][0] = 0.f; accS[nt][1] = 0.f; accS[nt][2] = 0.f; accS[nt][3] = 0.f;
    }

    // ---- interleaved: PV_j (32 rows x 128 dims) + S_{j+1} -------------------
    #pragma unroll
    for (int u = 0; u < 4; u++){
      {
        const int cA = u*2 + csel;
        uint32_t pa[2][4];
        #pragma unroll
        for (int mt = 0; mt < 2; mt++){
          int prow = pvm + mt*16 + rsel;
          uint32_t ad = sb + SM_P + prow*128 + ((cA ^ (prow & 7)) << 4);
          ldm4(pa[mt][0], pa[mt][1], pa[mt][2], pa[mt][3], ad);
        }
        #pragma unroll
        for (int g = 0; g < 8; g++){
          int vrow = pvd + g*16 + rsel;
          uint32_t bd = Vbase + vrow*128 + ((cA ^ (vrow & 7)) << 4);
          uint32_t r0, r1, r2, r3;
          ldm4(r0, r1, r2, r3, bd);
          uint32_t be[2] = {r0, r2}, bo[2] = {r1, r3};
          #pragma unroll
          for (int mt = 0; mt < 2; mt++){
            mma16816(accY[mt][2*g],   pa[mt], be);
            mma16816(accY[mt][2*g+1], pa[mt], bo);
          }
        }
      }
      if (do_s){
        #pragma unroll
        for (int s = 0; s < 4; s++){
          const int cA = (u*4 + s)*2 + csel;
          int qrow = qs + rsel;
          uint32_t ad = sb + SM_Q + qrow*512 + ((cA ^ (qrow & 7)) << 4);
          uint32_t qh[4];
          ldm4(qh[0], qh[1], qh[2], qh[3], ad);
          #pragma unroll
          for (int g = 0; g < 4; g++){
            int krow = g*16 + rsel;
            uint32_t bd = Kbase + krow*512 + ((cA ^ (krow & 7)) << 4);
            uint32_t r0, r1, r2, r3;
            ldm4(r0, r1, r2, r3, bd);
            uint32_t be[2] = {r0, r2}, bo[2] = {r1, r3};
            mma16816(accS[2*g],   qh, be);
            mma16816(accS[2*g+1], qh, bo);
          }
        }
      }
    }
  }

  cp_wait0();
  __syncthreads();            // all warps past final rescale before fbuf reuse
  // ---- publish l, then normalize + store ------------------------------------
  if ((lane & 3) == 0){
    fbuf[qs + (lane >> 2)]     = l0r;
    fbuf[qs + 8 + (lane >> 2)] = l1r;
  }
  __syncthreads();

  float* stg = (float*)sm;                     // [128 tokens][260]
  {
    float iA0 = 1.0f / fbuf[pvm + (lane >> 2)];
    float iB0 = 1.0f / fbuf[pvm + 8 + (lane >> 2)];
    float iA1 = 1.0f / fbuf[pvm + 16 + (lane >> 2)];
    float iB1 = 1.0f / fbuf[pvm + 24 + (lane >> 2)];
    int rA0 = pvm + (lane >> 2);
    #pragma unroll
    for (int nt = 0; nt < 16; nt++){
      int c = pvd + nt*8 + (lane & 3)*2;
      stg[rA0*260 + c]        = accY[0][nt][0]*iA0;
      stg[rA0*260 + c + 1]    = accY[0][nt][1]*iA0;
      stg[(rA0+8)*260 + c]    = accY[0][nt][2]*iB0;
      stg[(rA0+8)*260 + c + 1]= accY[0][nt][3]*iB0;
      stg[(rA0+16)*260 + c]     = accY[1][nt][0]*iA1;
      stg[(rA0+16)*260 + c + 1] = accY[1][nt][1]*iA1;
      stg[(rA0+24)*260 + c]     = accY[1][nt][2]*iB1;
      stg[(rA0+24)*260 + c + 1] = accY[1][nt][3]*iB1;
    }
  }
  __syncthreads();
  #pragma unroll
  for (int it = 0; it < 4; it++){
    int dim = it*64 + (tid >> 2);
    int seg = (tid & 3) * 32;
    float* op = out + (size_t)(b*CC + dim)*NN + q0 + seg;
    #pragma unroll
    for (int k = 0; k < 32; k += 4){
      float4 v;
      v.x = stg[(seg + k + 0)*260 + dim];
      v.y = stg[(seg + k + 1)*260 + dim];
      v.z = stg[(seg + k + 2)*260 + dim];
      v.w = stg[(seg + k + 3)*260 + dim];
      *(float4*)(op + k) = v;
    }
  }
}

// ---------------- launch ----------------------------------------------------
extern "C" void kernel_launch(void* const* d_in, const int* in_sizes, int n_in,
                              void* d_out, int out_size)
{
    const float* x  = (const float*)d_in[0];
    const float* wq = (const float*)d_in[1];
    const float* wk = (const float*)d_in[2];
    const float* wv = (const float*)d_in[3];
    float* out = (float*)d_out;

    __half *X, *Pt, *Wv, *T, *Vt;
    cudaGetSymbolAddress((void**)&X,  g_X);
    cudaGetSymbolAddress((void**)&Pt, g_Pt);  cudaGetSymbolAddress((void**)&Wv, g_Wv);
    cudaGetSymbolAddress((void**)&T,  g_T);   cudaGetSymbolAddress((void**)&Vt, g_Vt);

    const int SMEM_P = 69632;
    cudaFuncSetAttribute((const void*)gemm_mma<0>,
        cudaFuncAttributeMaxDynamicSharedMemorySize, SMEM_P);
    cudaFuncSetAttribute((const void*)gemm_mma<1>,
        cudaFuncAttributeMaxDynamicSharedMemorySize, SMEM_P);
    cudaFuncSetAttribute((const void*)flash_kernel,
        cudaFuncAttributeMaxDynamicSharedMemorySize, SM_FLASH);

    // 1) X = x + PE, fp16, (B,N,C)
    pe_transpose_kernel<<<dim3(NN/32, CC/32, BB), dim3(32,32)>>>(x);

    // 2) Pt = (0.0625*log2e) * Wq^T Wk  |  Wv -> fp16 (merged)
    prep_kernel<<<CC + CC*CC/256/1, CC>>>(wq, wk, wv);

    // 3) T = X @ Pt^T -> fp16 row-major
    gemm_mma<0><<<dim3(CC/128, MT/128, 1), 256, SMEM_P>>>(X, Pt, T, CC, CC, CC);

    // 4) Vt = (X @ Wv^T)^T -> fp16 (B,C,N)
    gemm_mma<1><<<dim3(CC/128, MT/128, 1), 256, SMEM_P>>>(X, Wv, Vt, CC, CC, CC);

    // 5) fused flash attention -> writes out (B,C,H,W) directly
    flash_kernel<<<dim3(NN/BQ, BB), 256, SM_FLASH>>>(out);
}

// round 15
// speedup vs baseline: 1.1153x; 1.0334x over previous
#include <cuda_runtime.h>
#include <cuda_fp16.h>
#include <stdint.h>
#include <math.h>

#define BB 4
#define CC 256
#define NN 4096          // H*W
#define MT (BB*NN)       // 16384 tokens
#define BQ 128           // queries per CTA (flash)
#define BKC 64           // keys per chunk (flash)
#define NCH (NN/BKC)     // 64 chunks

// ---------------- device scratch (no allocation) ---------------------------
static __device__ __half g_X [(size_t)MT*CC];              // X+PE, fp16 (B,N,C)
static __device__ __half g_Pt[CC*CC];
static __device__ __half g_Wv[CC*CC];
static __device__ __half g_T [(size_t)MT*CC];              // Q = X@Pt^T (B,N,C)
static __device__ __half g_Vt[(size_t)MT*CC];              // (B, C, N)

// ---------------- PTX helpers (base features only) -------------------------
__device__ __forceinline__ uint32_t smem_u32(const void* p){
  uint32_t a;
  asm("{ .reg .u64 t; cvta.to.shared.u64 t, %1; cvt.u32.u64 %0, t; }" : "=r"(a) : "l"(p));
  return a;
}
__device__ __forceinline__ void cp_async16(uint32_t dst, const void* src){
  asm volatile("cp.async.cg.shared.global [%0], [%1], 16;" :: "r"(dst), "l"(src));
}
__device__ __forceinline__ void cp_commit(){
  asm volatile("cp.async.commit_group;" ::: "memory");
}
__device__ __forceinline__ void cp_wait0(){
  asm volatile("cp.async.wait_group 0;" ::: "memory");
}
__device__ __forceinline__ void cp_wait1(){
  asm volatile("cp.async.wait_group 1;" ::: "memory");
}
__device__ __forceinline__ void cp_wait2(){
  asm volatile("cp.async.wait_group 2;" ::: "memory");
}
__device__ __forceinline__ void ldm4(uint32_t& r0, uint32_t& r1, uint32_t& r2,
                                     uint32_t& r3, uint32_t a){
  asm volatile("ldmatrix.sync.aligned.m8n8.x4.shared.b16 {%0,%1,%2,%3}, [%4];"
   : "=r"(r0), "=r"(r1), "=r"(r2), "=r"(r3) : "r"(a));
}
__device__ __forceinline__ void mma16816(float* d, const uint32_t* a, const uint32_t* b){
  asm volatile("mma.sync.aligned.m16n8k16.row.col.f32.f16.f16.f32 "
   "{%0,%1,%2,%3}, {%4,%5,%6,%7}, {%8,%9}, {%0,%1,%2,%3};"
   : "+f"(d[0]), "+f"(d[1]), "+f"(d[2]), "+f"(d[3])
   : "r"(a[0]), "r"(a[1]), "r"(a[2]), "r"(a[3]), "r"(b[0]), "r"(b[1]));
}
__device__ __forceinline__ uint32_t pack_f2h2(float a, float b){
  __half2 t = __floats2half2_rn(a, b);
  return *(uint32_t*)&t;
}
__device__ __forceinline__ float ex2(float x){
  float r;
  asm("ex2.approx.ftz.f32 %0, %1;" : "=f"(r) : "f"(x));
  return r;
}
// Packed half2 EX2: one MUFU op for two exponentials; returns f16x2 bits.
__device__ __forceinline__ uint32_t ex2_h2(float a, float b, float& s){
  uint32_t h = pack_f2h2(a, b);
  uint32_t r;
  asm("ex2.approx.f16x2 %0, %1;" : "=r"(r) : "r"(h));
  __half2 p = *(__half2*)&r;
  s += __half2float(p.x) + __half2float(p.y);
  return r;
}

// ---------------- kernel: x + PE -> fp16 (B,N,C) ----------------------------
__global__ void pe_transpose_kernel(const float* __restrict__ x) {
    __shared__ float tile[32][33];
    int b  = blockIdx.z;
    int c0 = blockIdx.y * 32, n0 = blockIdx.x * 32;
    int tx = threadIdx.x, ty = threadIdx.y;
    tile[ty][tx] = x[((size_t)(b*CC + c0 + ty))*NN + n0 + tx];
    __syncthreads();
    int c = c0 + tx, n = n0 + ty;
    int h = n >> 6, w = n & 63;
    int pos, cc;
    if (c < 128) { pos = w; cc = c; } else { pos = h; cc = c - 128; }
    int j = cc & 63;
    float inv = expf(-0.14391156831212787f * (float)j);
    float arg = (float)pos * inv;
    float pe = (cc >= 64) ? cosf(arg) : sinf(arg);
    g_X[((size_t)(b*NN + n))*CC + c] = __float2half_rn(tile[tx][ty] + pe);
}

// ---------------- merged: Pt = scale*Wq^T Wk  |  Wv -> fp16 ------------------
__global__ void prep_kernel(const float* __restrict__ wq,
                            const float* __restrict__ wk,
                            const float* __restrict__ wv){
  if (blockIdx.x < CC){
    int e = blockIdx.x, c = threadIdx.x;
    float acc = 0.f;
    for (int d = 0; d < CC; d++)
      acc += wq[d*CC + c] * wk[d*CC + e];
    g_Pt[e*CC + c] = __float2half_rn(acc * 0.09016844004f);  // 0.0625*log2(e)
  } else {
    int i = (blockIdx.x - CC)*256 + threadIdx.x;
    g_Wv[i] = __float2half_rn(wv[i]);
  }
}

// ---------------- mma.sync GEMM (NT), fp16 operands ------------------------
// MODE 0: fp16 out row-major (T projection)
// MODE 1: fp16 out transposed (B,C,N), coalesced uint4 stores (V projection)
template<int MODE>
__global__ void __launch_bounds__(256, 1)
gemm_mma(const __half* __restrict__ Am, const __half* __restrict__ Bm,
         __half* __restrict__ O1, int lda, int ldb, int K)
{
  extern __shared__ char sm[];
  const int tid  = threadIdx.x;
  const int lane = tid & 31, wid = tid >> 5;
  const int wm   = (wid >> 2) * 64;
  const int wn   = (wid & 3) * 32;

  const int m0 = blockIdx.y * 128, n0 = blockIdx.x * 128;
  const __half* aP = Am + (size_t)m0 * lda;
  const __half* bP = Bm + (size_t)n0 * ldb;

  const uint32_t sb = smem_u32(sm);

  auto load_chunk = [&](int ck, int stage){
    const int kt = ck << 6;
    const uint32_t base = sb + stage * 32768;
    #pragma unroll
    for (int u = 0; u < 4; u++){
      int idx = u*256 + tid;
      int r = idx >> 3, c = idx & 7;
      uint32_t dst = base + r*128 + ((c ^ (r & 7)) << 4);
      cp_async16(dst, aP + (size_t)r*lda + kt + c*8);
    }
    #pragma unroll
    for (int u = 0; u < 4; u++){
      int idx = u*256 + tid;
      int r = idx >> 3, c = idx & 7;
      uint32_t dst = base + 16384 + r*128 + ((c ^ (r & 7)) << 4);
      cp_async16(dst, bP + (size_t)r*ldb + kt + c*8);
    }
    cp_commit();
  };

  float acc[4][4][4] = {};
  const int nchunk = K >> 6;
  load_chunk(0, 0);

  for (int ck = 0; ck < nchunk; ck++){
    const int st = ck & 1;
    if (ck + 1 < nchunk){ load_chunk(ck + 1, st ^ 1); cp_wait1(); }
    else                { cp_wait0(); }
    __syncthreads();

    const uint32_t Abase = sb + st * 32768;
    const uint32_t Bbase = Abase + 16384;
    const int rsel = lane & 15;
    const int csel = lane >> 4;

    #pragma unroll
    for (int ks = 0; ks < 4; ks++){
      const int cA = ks*2 + csel;
      uint32_t ahf[4][4];
      #pragma unroll
      for (int mt = 0; mt < 4; mt++){
        int row = wm + mt*16 + rsel;
        uint32_t ad = Abase + row*128 + ((cA ^ (row & 7)) << 4);
        ldm4(ahf[mt][0], ahf[mt][1], ahf[mt][2], ahf[mt][3], ad);
      }
      uint32_t bhf[4][2];
      #pragma unroll
      for (int g = 0; g < 2; g++){
        int row = wn + g*16 + rsel;
        uint32_t bd = Bbase + row*128 + ((cA ^ (row & 7)) << 4);
        uint32_t r0, r1, r2, r3;
        ldm4(r0, r1, r2, r3, bd);
        bhf[g*2][0] = r0; bhf[g*2][1] = r2;
        bhf[g*2+1][0] = r1; bhf[g*2+1][1] = r3;
      }
      #pragma unroll
      for (int mt = 0; mt < 4; mt++)
        #pragma unroll
        for (int nt = 0; nt < 4; nt++)
          mma16816(acc[mt][nt], ahf[mt], bhf[nt]);
    }
    __syncthreads();
  }

  if (MODE == 0){
    #pragma unroll
    for (int mt = 0; mt < 4; mt++)
      #pragma unroll
      for (int nt = 0; nt < 4; nt++){
        int r = m0 + wm + mt*16 + (lane >> 2);
        int c = n0 + wn + nt*8  + (lane & 3)*2;
        *(__half2*)(O1 + (size_t)r*CC + c) =
            __floats2half2_rn(acc[mt][nt][0], acc[mt][nt][1]);
        *(__half2*)(O1 + (size_t)(r+8)*CC + c) =
            __floats2half2_rn(acc[mt][nt][2], acc[mt][nt][3]);
      }
  } else {
    float* stg = (float*)sm;             // [128 tokens][132 channels]
    #pragma unroll
    for (int mt = 0; mt < 4; mt++)
      #pragma unroll
      for (int nt = 0; nt < 4; nt++){
        int r = wm + mt*16 + (lane >> 2);
        int c = wn + nt*8  + (lane & 3)*2;
        stg[r*132 + c]     = acc[mt][nt][0];
        stg[r*132 + c + 1] = acc[mt][nt][1];
        stg[(r+8)*132 + c]     = acc[mt][nt][2];
        stg[(r+8)*132 + c + 1] = acc[mt][nt][3];
      }
    __syncthreads();
    // Coalesced transpose store: 16 consecutive lanes cover one channel's
    // 128 tokens in 16B uint4 chunks (8 fp16 each).
    int b = m0 / NN, tok0 = m0 % NN;
    #pragma unroll
    for (int it = 0; it < 8; it++){
      int idx = it*256 + tid;            // 128 ch x 16 groups
      int ch  = idx >> 4;
      int grp = (idx & 15) * 8;          // token group base
      uint32_t h4[4];
      #pragma unroll
      for (int k = 0; k < 4; k++)
        h4[k] = pack_f2h2(stg[(grp + 2*k)*132 + ch],
                          stg[(grp + 2*k + 1)*132 + ch]);
      *(uint4*)(O1 + (size_t)(b*CC + n0 + ch)*NN + tok0 + grp) =
          *(uint4*)h4;
    }
  }
}

// ---------------- fused flash attention (R12 structure — best known) --------
// BQ=128 q/CTA, 8 warps. S: warp = 16 rows x 64 keys (warp-local softmax).
// PV: warp = 32 rows x 128 dims; P via 16KB smem.
// smem: Q 64K | K ring 2x32K | V ring 2x32K | P 16K | f/l 512B
#define SM_Q    0
#define SM_KR   65536
#define SM_VR   131072
#define SM_P    196608
#define SM_F    212992
#define SM_FLASH 213504

__global__ void __launch_bounds__(256, 1)
flash_kernel(float* __restrict__ out)
{
  extern __shared__ char sm[];
  const uint32_t sb = smem_u32(sm);
  float* fbuf = (float*)(sm + SM_F);    // per-row f (per chunk) then l (final)
  const int tid = threadIdx.x, lane = tid & 31, wid = tid >> 5;
  const int b  = blockIdx.y;
  const int q0 = blockIdx.x * BQ;
  const int qs = wid * 16;              // softmax/S row base
  const int mg = wid >> 1, dg = wid & 1;
  const int pvm = mg * 32;              // PV row base
  const int pvd = dg * 128;             // PV dim base
  const int rsel = lane & 15, csel = lane >> 4;

  auto load_K = [&](int j){
    int k0 = j * BKC;
    uint32_t base = sb + SM_KR + (j & 1)*32768;
    #pragma unroll
    for (int u = 0; u < 8; u++){
      int idx = u*256 + tid;            // 64 rows x 32 chunks
      int r = idx >> 5, c = idx & 31;
      uint32_t dst = base + r*512 + ((c ^ (r & 7)) << 4);
      cp_async16(dst, g_X + ((size_t)(b*NN + k0 + r))*CC + c*8);
    }
    cp_commit();
  };
  auto load_V = [&](int j){
    int k0 = j * BKC;
    uint32_t base = sb + SM_VR + (j & 1)*32768;
    #pragma unroll
    for (int u = 0; u < 8; u++){
      int idx = u*256 + tid;            // 256 rows x 8 chunks
      int r = idx >> 3, c = idx & 7;
      uint32_t dst = base + r*128 + ((c ^ (r & 7)) << 4);
      cp_async16(dst, g_Vt + ((size_t)(b*CC + r))*NN + k0 + c*8);
    }
    cp_commit();
  };

  // prologue: [Q], [K0], [V0], [K1]
  #pragma unroll
  for (int u = 0; u < 16; u++){
    int idx = u*256 + tid;              // 128 rows x 32 chunks
    int r = idx >> 5, c = idx & 31;
    uint32_t dst = sb + SM_Q + r*512 + ((c ^ (r & 7)) << 4);
    cp_async16(dst, g_T + ((size_t)(b*NN + q0 + r))*CC + c*8);
  }
  cp_commit();
  load_K(0);
  load_V(0);
  load_K(1);

  float m0r = -1e30f, m1r = -1e30f, l0r = 0.f, l1r = 0.f;
  float accY[2][16][4] = {};
  float accS[8][4] = {};

  cp_wait2();                 // Q, K0 ready (pending V0, K1)
  __syncthreads();

  // ---- S_0 ----
  {
    const uint32_t Kbase = sb + SM_KR;
    #pragma unroll 4
    for (int ks = 0; ks < 16; ks++){
      const int cA = ks*2 + csel;
      int qrow = qs + rsel;
      uint32_t ad = sb + SM_Q + qrow*512 + ((cA ^ (qrow & 7)) << 4);
      uint32_t qh[4];
      ldm4(qh[0], qh[1], qh[2], qh[3], ad);
      #pragma unroll
      for (int g = 0; g < 4; g++){
        int krow = g*16 + rsel;
        uint32_t bd = Kbase + krow*512 + ((cA ^ (krow & 7)) << 4);
        uint32_t r0, r1, r2, r3;
        ldm4(r0, r1, r2, r3, bd);
        uint32_t be[2] = {r0, r2}, bo[2] = {r1, r3};
        mma16816(accS[2*g],   qh, be);
        mma16816(accS[2*g+1], qh, bo);
      }
    }
  }

  for (int j = 0; j < NCH; j++){
    // ---- softmax_j (log2 domain) -------------------------------------------
    float mx0 = -1e30f, mx1 = -1e30f;
    #pragma unroll
    for (int nt = 0; nt < 8; nt++){
      mx0 = fmaxf(mx0, fmaxf(accS[nt][0], accS[nt][1]));
      mx1 = fmaxf(mx1, fmaxf(accS[nt][2], accS[nt][3]));
    }
    mx0 = fmaxf(mx0, __shfl_xor_sync(0xffffffffu, mx0, 1));
    mx0 = fmaxf(mx0, __shfl_xor_sync(0xffffffffu, mx0, 2));
    mx1 = fmaxf(mx1, __shfl_xor_sync(0xffffffffu, mx1, 1));
    mx1 = fmaxf(mx1, __shfl_xor_sync(0xffffffffu, mx1, 2));
    float mn0 = fmaxf(m0r, mx0), mn1 = fmaxf(m1r, mx1);
    float f0 = ex2(m0r - mn0), f1 = ex2(m1r - mn1);
    m0r = mn0; m1r = mn1;

    uint32_t pp[8][2];
    float s0 = 0.f, s1 = 0.f;
    #pragma unroll
    for (int nt = 0; nt < 8; nt++){
      pp[nt][0] = ex2_h2(accS[nt][0] - mn0, accS[nt][1] - mn0, s0);
      pp[nt][1] = ex2_h2(accS[nt][2] - mn1, accS[nt][3] - mn1, s1);
    }
    s0 += __shfl_xor_sync(0xffffffffu, s0, 1);
    s0 += __shfl_xor_sync(0xffffffffu, s0, 2);
    s1 += __shfl_xor_sync(0xffffffffu, s1, 1);
    s1 += __shfl_xor_sync(0xffffffffu, s1, 2);
    l0r = l0r*f0 + s0;
    l1r = l1r*f1 + s1;

    __syncthreads();        // (A) all warps done with P_{j-1}, V_{j-1}, K_j

    // ---- publish P_j (16 rows x 64 keys per warp) + f_j --------------------
    {
      int rA = qs + (lane >> 2), rB = rA + 8;
      #pragma unroll
      for (int nt = 0; nt < 8; nt++){
        uint32_t wi = (lane & 3) * 4;
        uint32_t oA = SM_P + rA*128 + (((uint32_t)(nt ^ (rA & 7))) << 4) + wi;
        uint32_t oB = SM_P + rB*128 + (((uint32_t)(nt ^ (rB & 7))) << 4) + wi;
        *(uint32_t*)(sm + oA) = pp[nt][0];
        *(uint32_t*)(sm + oB) = pp[nt][1];
      }
      if ((lane & 3) == 0){
        fbuf[rA] = f0;
        fbuf[rB] = f1;
      }
    }

    load_V(j + 1 < NCH ? j + 1 : NCH - 1);   // -> vslot (j+1)&1
    load_K(j + 2 < NCH ? j + 2 : NCH - 1);   // -> kslot j&1
    cp_wait2();                              // V_j, K_{j+1} ready
    __syncthreads();        // (B) P_j, f_j visible

    // ---- rescale accY (rows pvm..pvm+31) ------------------------------------
    {
      float fA0 = fbuf[pvm + (lane >> 2)];
      float fB0 = fbuf[pvm + 8 + (lane >> 2)];
      float fA1 = fbuf[pvm + 16 + (lane >> 2)];
      float fB1 = fbuf[pvm + 24 + (lane >> 2)];
      bool need = (fA0 != 1.f) || (fB0 != 1.f) || (fA1 != 1.f) || (fB1 != 1.f);
      if (__any_sync(0xffffffffu, need)){
        #pragma unroll
        for (int nt = 0; nt < 16; nt++){
          accY[0][nt][0] *= fA0; accY[0][nt][1] *= fA0;
          accY[0][nt][2] *= fB0; accY[0][nt][3] *= fB0;
          accY[1][nt][0] *= fA1; accY[1][nt][1] *= fA1;
          accY[1][nt][2] *= fB1; accY[1][nt][3] *= fB1;
        }
      }
    }

    const uint32_t Vbase = sb + SM_VR + (j & 1)*32768;
    const uint32_t Kbase = sb + SM_KR + ((j + 1) & 1)*32768;
    const bool do_s = (j + 1 < NCH);

    #pragma unroll
    for (int nt = 0; nt < 8; nt++){
      accS[nt][0] = 0.f; accS[nt][1] = 0.f; accS[nt][2] = 0.f; accS[nt][3] = 0.f;
    }

    // ---- interleaved: PV_j (32 rows x 128 dims) + S_{j+1} -------------------
    #pragma unroll
    for (int u = 0; u < 4; u++){
      {
        const int cA = u*2 + csel;
        uint32_t pa[2][4];
        #pragma unroll
        for (int mt = 0; mt < 2; mt++){
          int prow = pvm + mt*16 + rsel;
          uint32_t ad = sb + SM_P + prow*128 + ((cA ^ (prow & 7)) << 4);
          ldm4(pa[mt][0], pa[mt][1], pa[mt][2], pa[mt][3], ad);
        }
        #pragma unroll
        for (int g = 0; g < 8; g++){
          int vrow = pvd + g*16 + rsel;
          uint32_t bd = Vbase + vrow*128 + ((cA ^ (vrow & 7)) << 4);
          uint32_t r0, r1, r2, r3;
          ldm4(r0, r1, r2, r3, bd);
          uint32_t be[2] = {r0, r2}, bo[2] = {r1, r3};
          #pragma unroll
          for (int mt = 0; mt < 2; mt++){
            mma16816(accY[mt][2*g],   pa[mt], be);
            mma16816(accY[mt][2*g+1], pa[mt], bo);
          }
        }
      }
      if (do_s){
        #pragma unroll
        for (int s = 0; s < 4; s++){
          const int cA = (u*4 + s)*2 + csel;
          int qrow = qs + rsel;
          uint32_t ad = sb + SM_Q + qrow*512 + ((cA ^ (qrow & 7)) << 4);
          uint32_t qh[4];
          ldm4(qh[0], qh[1], qh[2], qh[3], ad);
          #pragma unroll
          for (int g = 0; g < 4; g++){
            int krow = g*16 + rsel;
            uint32_t bd = Kbase + krow*512 + ((cA ^ (krow & 7)) << 4);
            uint32_t r0, r1, r2, r3;
            ldm4(r0, r1, r2, r3, bd);
            uint32_t be[2] = {r0, r2}, bo[2] = {r1, r3};
            mma16816(accS[2*g],   qh, be);
            mma16816(accS[2*g+1], qh, bo);
          }
        }
      }
    }
  }

  cp_wait0();
  // ---- publish l, then normalize + store ------------------------------------
  if ((lane & 3) == 0){
    fbuf[qs + (lane >> 2)]     = l0r;
    fbuf[qs + 8 + (lane >> 2)] = l1r;
  }
  __syncthreads();

  float* stg = (float*)sm;                     // [128 tokens][260]
  {
    float iA0 = 1.0f / fbuf[pvm + (lane >> 2)];
    float iB0 = 1.0f / fbuf[pvm + 8 + (lane >> 2)];
    float iA1 = 1.0f / fbuf[pvm + 16 + (lane >> 2)];
    float iB1 = 1.0f / fbuf[pvm + 24 + (lane >> 2)];
    int rA0 = pvm + (lane >> 2);
    #pragma unroll
    for (int nt = 0; nt < 16; nt++){
      int c = pvd + nt*8 + (lane & 3)*2;
      stg[rA0*260 + c]        = accY[0][nt][0]*iA0;
      stg[rA0*260 + c + 1]    = accY[0][nt][1]*iA0;
      stg[(rA0+8)*260 + c]    = accY[0][nt][2]*iB0;
      stg[(rA0+8)*260 + c + 1]= accY[0][nt][3]*iB0;
      stg[(rA0+16)*260 + c]     = accY[1][nt][0]*iA1;
      stg[(rA0+16)*260 + c + 1] = accY[1][nt][1]*iA1;
      stg[(rA0+24)*260 + c]     = accY[1][nt][2]*iB1;
      stg[(rA0+24)*260 + c + 1] = accY[1][nt][3]*iB1;
    }
  }
  __syncthreads();
  #pragma unroll
  for (int it = 0; it < 4; it++){
    int dim = it*64 + (tid >> 2);
    int seg = (tid & 3) * 32;
    float* op = out + (size_t)(b*CC + dim)*NN + q0 + seg;
    #pragma unroll
    for (int k = 0; k < 32; k += 4){
      float4 v;
      v.x = stg[(seg + k + 0)*260 + dim];
      v.y = stg[(seg + k + 1)*260 + dim];
      v.z = stg[(seg + k + 2)*260 + dim];
      v.w = stg[(seg + k + 3)*260 + dim];
      *(float4*)(op + k) = v;
    }
  }
}

// ---------------- launch ----------------------------------------------------
extern "C" void kernel_launch(void* const* d_in, const int* in_sizes, int n_in,
                              void* d_out, int out_size)
{
    const float* x  = (const float*)d_in[0];
    const float* wq = (const float*)d_in[1];
    const float* wk = (const float*)d_in[2];
    const float* wv = (const float*)d_in[3];
    float* out = (float*)d_out;

    __half *X, *Pt, *Wv, *T, *Vt;
    cudaGetSymbolAddress((void**)&X,  g_X);
    cudaGetSymbolAddress((void**)&Pt, g_Pt);  cudaGetSymbolAddress((void**)&Wv, g_Wv);
    cudaGetSymbolAddress((void**)&T,  g_T);   cudaGetSymbolAddress((void**)&Vt, g_Vt);

    const int SMEM_P = 69632;
    cudaFuncSetAttribute((const void*)gemm_mma<0>,
        cudaFuncAttributeMaxDynamicSharedMemorySize, SMEM_P);
    cudaFuncSetAttribute((const void*)gemm_mma<1>,
        cudaFuncAttributeMaxDynamicSharedMemorySize, SMEM_P);
    cudaFuncSetAttribute((const void*)flash_kernel,
        cudaFuncAttributeMaxDynamicSharedMemorySize, SM_FLASH);

    // 1) X = x + PE, fp16, (B,N,C)
    pe_transpose_kernel<<<dim3(NN/32, CC/32, BB), dim3(32,32)>>>(x);

    // 2) Pt = (0.0625*log2e) * Wq^T Wk  |  Wv -> fp16 (merged)
    prep_kernel<<<2*CC, CC>>>(wq, wk, wv);

    // 3) T = X @ Pt^T -> fp16 row-major
    gemm_mma<0><<<dim3(CC/128, MT/128, 1), 256, SMEM_P>>>(X, Pt, T, CC, CC, CC);

    // 4) Vt = (X @ Wv^T)^T -> fp16 (B,C,N), coalesced stores
    gemm_mma<1><<<dim3(CC/128, MT/128, 1), 256, SMEM_P>>>(X, Wv, Vt, CC, CC, CC);

    // 5) fused flash attention -> writes out (B,C,H,W) directly
    flash_kernel<<<dim3(NN/BQ, BB), 256, SM_FLASH>>>(out);
}

// round 16
// speedup vs baseline: 1.1327x; 1.0156x over previous
#include <cuda_runtime.h>
#include <cuda_fp16.h>
#include <stdint.h>
#include <math.h>

#define BB 4
#define CC 256
#define NN 4096          // H*W
#define MT (BB*NN)       // 16384 tokens
#define BQ 128           // queries per CTA (flash)
#define BKC 64           // keys per chunk (flash)
#define NCH (NN/BKC)     // 64 chunks
#define SP 133           // staging pitch (odd -> no 16-way bank conflicts)

// ---------------- device scratch (no allocation) ---------------------------
static __device__ __half g_X [(size_t)MT*CC];              // X+PE, fp16 (B,N,C)
static __device__ __half g_Pt[CC*CC];
static __device__ __half g_Wv[CC*CC];
static __device__ __half g_T [(size_t)MT*CC];              // Q = X@Pt^T (B,N,C)
static __device__ __half g_Vt[(size_t)MT*CC];              // (B, C, N)

// ---------------- PTX helpers (base features only) -------------------------
__device__ __forceinline__ uint32_t smem_u32(const void* p){
  uint32_t a;
  asm("{ .reg .u64 t; cvta.to.shared.u64 t, %1; cvt.u32.u64 %0, t; }" : "=r"(a) : "l"(p));
  return a;
}
__device__ __forceinline__ void cp_async16(uint32_t dst, const void* src){
  asm volatile("cp.async.cg.shared.global [%0], [%1], 16;" :: "r"(dst), "l"(src));
}
__device__ __forceinline__ void cp_commit(){
  asm volatile("cp.async.commit_group;" ::: "memory");
}
__device__ __forceinline__ void cp_wait0(){
  asm volatile("cp.async.wait_group 0;" ::: "memory");
}
__device__ __forceinline__ void cp_wait1(){
  asm volatile("cp.async.wait_group 1;" ::: "memory");
}
__device__ __forceinline__ void cp_wait2(){
  asm volatile("cp.async.wait_group 2;" ::: "memory");
}
__device__ __forceinline__ void ldm4(uint32_t& r0, uint32_t& r1, uint32_t& r2,
                                     uint32_t& r3, uint32_t a){
  asm volatile("ldmatrix.sync.aligned.m8n8.x4.shared.b16 {%0,%1,%2,%3}, [%4];"
   : "=r"(r0), "=r"(r1), "=r"(r2), "=r"(r3) : "r"(a));
}
__device__ __forceinline__ void mma16816(float* d, const uint32_t* a, const uint32_t* b){
  asm volatile("mma.sync.aligned.m16n8k16.row.col.f32.f16.f16.f32 "
   "{%0,%1,%2,%3}, {%4,%5,%6,%7}, {%8,%9}, {%0,%1,%2,%3};"
   : "+f"(d[0]), "+f"(d[1]), "+f"(d[2]), "+f"(d[3])
   : "r"(a[0]), "r"(a[1]), "r"(a[2]), "r"(a[3]), "r"(b[0]), "r"(b[1]));
}
__device__ __forceinline__ uint32_t pack_f2h2(float a, float b){
  __half2 t = __floats2half2_rn(a, b);
  return *(uint32_t*)&t;
}
__device__ __forceinline__ float ex2(float x){
  float r;
  asm("ex2.approx.ftz.f32 %0, %1;" : "=f"(r) : "f"(x));
  return r;
}
// Packed half2 EX2: one MUFU op for two exponentials; returns f16x2 bits.
__device__ __forceinline__ uint32_t ex2_h2(float a, float b, float& s){
  uint32_t h = pack_f2h2(a, b);
  uint32_t r;
  asm("ex2.approx.f16x2 %0, %1;" : "=r"(r) : "r"(h));
  __half2 p = *(__half2*)&r;
  s += __half2float(p.x) + __half2float(p.y);
  return r;
}

// ---------------- kernel: x + PE -> fp16 (B,N,C) ----------------------------
__global__ void pe_transpose_kernel(const float* __restrict__ x) {
    __shared__ float tile[32][33];
    int b  = blockIdx.z;
    int c0 = blockIdx.y * 32, n0 = blockIdx.x * 32;
    int tx = threadIdx.x, ty = threadIdx.y;
    tile[ty][tx] = x[((size_t)(b*CC + c0 + ty))*NN + n0 + tx];
    __syncthreads();
    int c = c0 + tx, n = n0 + ty;
    int h = n >> 6, w = n & 63;
    int pos, cc;
    if (c < 128) { pos = w; cc = c; } else { pos = h; cc = c - 128; }
    int j = cc & 63;
    float inv = expf(-0.14391156831212787f * (float)j);
    float arg = (float)pos * inv;
    float pe = (cc >= 64) ? cosf(arg) : sinf(arg);
    g_X[((size_t)(b*NN + n))*CC + c] = __float2half_rn(tile[tx][ty] + pe);
}

// ---------------- merged: Pt = scale*Wq^T Wk  |  Wv -> fp16 ------------------
__global__ void prep_kernel(const float* __restrict__ wq,
                            const float* __restrict__ wk,
                            const float* __restrict__ wv){
  if (blockIdx.x < CC){
    int e = blockIdx.x, c = threadIdx.x;
    float acc = 0.f;
    for (int d = 0; d < CC; d++)
      acc += wq[d*CC + c] * wk[d*CC + e];
    g_Pt[e*CC + c] = __float2half_rn(acc * 0.09016844004f);  // 0.0625*log2(e)
  } else {
    int i = (blockIdx.x - CC)*256 + threadIdx.x;
    g_Wv[i] = __float2half_rn(wv[i]);
  }
}

// ---------------- mma.sync GEMM (NT), fp16 operands ------------------------
// MODE 0: fp16 out row-major (T projection)
// MODE 1: fp16 out transposed (B,C,N), coalesced uint4 stores (V projection)
template<int MODE>
__global__ void __launch_bounds__(256, 1)
gemm_mma(const __half* __restrict__ Am, const __half* __restrict__ Bm,
         __half* __restrict__ O1, int lda, int ldb, int K)
{
  extern __shared__ char sm[];
  const int tid  = threadIdx.x;
  const int lane = tid & 31, wid = tid >> 5;
  const int wm   = (wid >> 2) * 64;
  const int wn   = (wid & 3) * 32;

  const int m0 = blockIdx.y * 128, n0 = blockIdx.x * 128;
  const __half* aP = Am + (size_t)m0 * lda;
  const __half* bP = Bm + (size_t)n0 * ldb;

  const uint32_t sb = smem_u32(sm);

  auto load_chunk = [&](int ck, int stage){
    const int kt = ck << 6;
    const uint32_t base = sb + stage * 32768;
    #pragma unroll
    for (int u = 0; u < 4; u++){
      int idx = u*256 + tid;
      int r = idx >> 3, c = idx & 7;
      uint32_t dst = base + r*128 + ((c ^ (r & 7)) << 4);
      cp_async16(dst, aP + (size_t)r*lda + kt + c*8);
    }
    #pragma unroll
    for (int u = 0; u < 4; u++){
      int idx = u*256 + tid;
      int r = idx >> 3, c = idx & 7;
      uint32_t dst = base + 16384 + r*128 + ((c ^ (r & 7)) << 4);
      cp_async16(dst, bP + (size_t)r*ldb + kt + c*8);
    }
    cp_commit();
  };

  float acc[4][4][4] = {};
  const int nchunk = K >> 6;
  load_chunk(0, 0);

  for (int ck = 0; ck < nchunk; ck++){
    const int st = ck & 1;
    if (ck + 1 < nchunk){ load_chunk(ck + 1, st ^ 1); cp_wait1(); }
    else                { cp_wait0(); }
    __syncthreads();

    const uint32_t Abase = sb + st * 32768;
    const uint32_t Bbase = Abase + 16384;
    const int rsel = lane & 15;
    const int csel = lane >> 4;

    #pragma unroll
    for (int ks = 0; ks < 4; ks++){
      const int cA = ks*2 + csel;
      uint32_t ahf[4][4];
      #pragma unroll
      for (int mt = 0; mt < 4; mt++){
        int row = wm + mt*16 + rsel;
        uint32_t ad = Abase + row*128 + ((cA ^ (row & 7)) << 4);
        ldm4(ahf[mt][0], ahf[mt][1], ahf[mt][2], ahf[mt][3], ad);
      }
      uint32_t bhf[4][2];
      #pragma unroll
      for (int g = 0; g < 2; g++){
        int row = wn + g*16 + rsel;
        uint32_t bd = Bbase + row*128 + ((cA ^ (row & 7)) << 4);
        uint32_t r0, r1, r2, r3;
        ldm4(r0, r1, r2, r3, bd);
        bhf[g*2][0] = r0; bhf[g*2][1] = r2;
        bhf[g*2+1][0] = r1; bhf[g*2+1][1] = r3;
      }
      #pragma unroll
      for (int mt = 0; mt < 4; mt++)
        #pragma unroll
        for (int nt = 0; nt < 4; nt++)
          mma16816(acc[mt][nt], ahf[mt], bhf[nt]);
    }
    __syncthreads();
  }

  if (MODE == 0){
    #pragma unroll
    for (int mt = 0; mt < 4; mt++)
      #pragma unroll
      for (int nt = 0; nt < 4; nt++){
        int r = m0 + wm + mt*16 + (lane >> 2);
        int c = n0 + wn + nt*8  + (lane & 3)*2;
        *(__half2*)(O1 + (size_t)r*CC + c) =
            __floats2half2_rn(acc[mt][nt][0], acc[mt][nt][1]);
        *(__half2*)(O1 + (size_t)(r+8)*CC + c) =
            __floats2half2_rn(acc[mt][nt][2], acc[mt][nt][3]);
      }
  } else {
    float* stg = (float*)sm;             // [128 tokens][SP channels], SP odd
    #pragma unroll
    for (int mt = 0; mt < 4; mt++)
      #pragma unroll
      for (int nt = 0; nt < 4; nt++){
        int r = wm + mt*16 + (lane >> 2);
        int c = wn + nt*8  + (lane & 3)*2;
        stg[r*SP + c]     = acc[mt][nt][0];
        stg[r*SP + c + 1] = acc[mt][nt][1];
        stg[(r+8)*SP + c]     = acc[mt][nt][2];
        stg[(r+8)*SP + c + 1] = acc[mt][nt][3];
      }
    __syncthreads();
    // Coalesced transpose store: 16 consecutive lanes cover one channel's
    // 128 tokens in 16B uint4 chunks (8 fp16 each).
    int b = m0 / NN, tok0 = m0 % NN;
    #pragma unroll
    for (int it = 0; it < 8; it++){
      int idx = it*256 + tid;            // 128 ch x 16 groups
      int ch  = idx >> 4;
      int grp = (idx & 15) * 8;          // token group base
      uint32_t h4[4];
      #pragma unroll
      for (int k = 0; k < 4; k++)
        h4[k] = pack_f2h2(stg[(grp + 2*k)*SP + ch],
                          stg[(grp + 2*k + 1)*SP + ch]);
      *(uint4*)(O1 + (size_t)(b*CC + n0 + ch)*NN + tok0 + grp) =
          *(uint4*)h4;
    }
  }
}

// ---------------- fused flash attention (R12 structure — best known) --------
// BQ=128 q/CTA, 8 warps. S: warp = 16 rows x 64 keys (warp-local softmax).
// PV: warp = 32 rows x 128 dims; P via 16KB smem.
// smem: Q 64K | K ring 2x32K | V ring 2x32K | P 16K | f/l 512B
#define SM_Q    0
#define SM_KR   65536
#define SM_VR   131072
#define SM_P    196608
#define SM_F    212992
#define SM_FLASH 213504

__global__ void __launch_bounds__(256, 1)
flash_kernel(float* __restrict__ out)
{
  extern __shared__ char sm[];
  const uint32_t sb = smem_u32(sm);
  float* fbuf = (float*)(sm + SM_F);    // per-row f (per chunk) then l (final)
  const int tid = threadIdx.x, lane = tid & 31, wid = tid >> 5;
  const int b  = blockIdx.y;
  const int q0 = blockIdx.x * BQ;
  const int qs = wid * 16;              // softmax/S row base
  const int mg = wid >> 1, dg = wid & 1;
  const int pvm = mg * 32;              // PV row base
  const int pvd = dg * 128;             // PV dim base
  const int rsel = lane & 15, csel = lane >> 4;

  auto load_K = [&](int j){
    int k0 = j * BKC;
    uint32_t base = sb + SM_KR + (j & 1)*32768;
    #pragma unroll
    for (int u = 0; u < 8; u++){
      int idx = u*256 + tid;            // 64 rows x 32 chunks
      int r = idx >> 5, c = idx & 31;
      uint32_t dst = base + r*512 + ((c ^ (r & 7)) << 4);
      cp_async16(dst, g_X + ((size_t)(b*NN + k0 + r))*CC + c*8);
    }
    cp_commit();
  };
  auto load_V = [&](int j){
    int k0 = j * BKC;
    uint32_t base = sb + SM_VR + (j & 1)*32768;
    #pragma unroll
    for (int u = 0; u < 8; u++){
      int idx = u*256 + tid;            // 256 rows x 8 chunks
      int r = idx >> 3, c = idx & 7;
      uint32_t dst = base + r*128 + ((c ^ (r & 7)) << 4);
      cp_async16(dst, g_Vt + ((size_t)(b*CC + r))*NN + k0 + c*8);
    }
    cp_commit();
  };

  // prologue: [Q], [K0], [V0], [K1]
  #pragma unroll
  for (int u = 0; u < 16; u++){
    int idx = u*256 + tid;              // 128 rows x 32 chunks
    int r = idx >> 5, c = idx & 31;
    uint32_t dst = sb + SM_Q + r*512 + ((c ^ (r & 7)) << 4);
    cp_async16(dst, g_T + ((size_t)(b*NN + q0 + r))*CC + c*8);
  }
  cp_commit();
  load_K(0);
  load_V(0);
  load_K(1);

  float m0r = -1e30f, m1r = -1e30f, l0r = 0.f, l1r = 0.f;
  float accY[2][16][4] = {};
  float accS[8][4] = {};

  cp_wait2();                 // Q, K0 ready (pending V0, K1)
  __syncthreads();

  // ---- S_0 ----
  {
    const uint32_t Kbase = sb + SM_KR;
    #pragma unroll 4
    for (int ks = 0; ks < 16; ks++){
      const int cA = ks*2 + csel;
      int qrow = qs + rsel;
      uint32_t ad = sb + SM_Q + qrow*512 + ((cA ^ (qrow & 7)) << 4);
      uint32_t qh[4];
      ldm4(qh[0], qh[1], qh[2], qh[3], ad);
      #pragma unroll
      for (int g = 0; g < 4; g++){
        int krow = g*16 + rsel;
        uint32_t bd = Kbase + krow*512 + ((cA ^ (krow & 7)) << 4);
        uint32_t r0, r1, r2, r3;
        ldm4(r0, r1, r2, r3, bd);
        uint32_t be[2] = {r0, r2}, bo[2] = {r1, r3};
        mma16816(accS[2*g],   qh, be);
        mma16816(accS[2*g+1], qh, bo);
      }
    }
  }

  for (int j = 0; j < NCH; j++){
    // ---- softmax_j (log2 domain) -------------------------------------------
    float mx0 = -1e30f, mx1 = -1e30f;
    #pragma unroll
    for (int nt = 0; nt < 8; nt++){
      mx0 = fmaxf(mx0, fmaxf(accS[nt][0], accS[nt][1]));
      mx1 = fmaxf(mx1, fmaxf(accS[nt][2], accS[nt][3]));
    }
    mx0 = fmaxf(mx0, __shfl_xor_sync(0xffffffffu, mx0, 1));
    mx0 = fmaxf(mx0, __shfl_xor_sync(0xffffffffu, mx0, 2));
    mx1 = fmaxf(mx1, __shfl_xor_sync(0xffffffffu, mx1, 1));
    mx1 = fmaxf(mx1, __shfl_xor_sync(0xffffffffu, mx1, 2));
    float mn0 = fmaxf(m0r, mx0), mn1 = fmaxf(m1r, mx1);
    float f0 = ex2(m0r - mn0), f1 = ex2(m1r - mn1);
    m0r = mn0; m1r = mn1;

    uint32_t pp[8][2];
    float s0 = 0.f, s1 = 0.f;
    #pragma unroll
    for (int nt = 0; nt < 8; nt++){
      pp[nt][0] = ex2_h2(accS[nt][0] - mn0, accS[nt][1] - mn0, s0);
      pp[nt][1] = ex2_h2(accS[nt][2] - mn1, accS[nt][3] - mn1, s1);
    }
    s0 += __shfl_xor_sync(0xffffffffu, s0, 1);
    s0 += __shfl_xor_sync(0xffffffffu, s0, 2);
    s1 += __shfl_xor_sync(0xffffffffu, s1, 1);
    s1 += __shfl_xor_sync(0xffffffffu, s1, 2);
    l0r = l0r*f0 + s0;
    l1r = l1r*f1 + s1;

    __syncthreads();        // (A) all warps done with P_{j-1}, V_{j-1}, K_j

    // ---- publish P_j (16 rows x 64 keys per warp) + f_j --------------------
    {
      int rA = qs + (lane >> 2), rB = rA + 8;
      #pragma unroll
      for (int nt = 0; nt < 8; nt++){
        uint32_t wi = (lane & 3) * 4;
        uint32_t oA = SM_P + rA*128 + (((uint32_t)(nt ^ (rA & 7))) << 4) + wi;
        uint32_t oB = SM_P + rB*128 + (((uint32_t)(nt ^ (rB & 7))) << 4) + wi;
        *(uint32_t*)(sm + oA) = pp[nt][0];
        *(uint32_t*)(sm + oB) = pp[nt][1];
      }
      if ((lane & 3) == 0){
        fbuf[rA] = f0;
        fbuf[rB] = f1;
      }
    }

    load_V(j + 1 < NCH ? j + 1 : NCH - 1);   // -> vslot (j+1)&1
    load_K(j + 2 < NCH ? j + 2 : NCH - 1);   // -> kslot j&1
    cp_wait2();                              // V_j, K_{j+1} ready
    __syncthreads();        // (B) P_j, f_j visible

    // ---- rescale accY (rows pvm..pvm+31) ------------------------------------
    {
      float fA0 = fbuf[pvm + (lane >> 2)];
      float fB0 = fbuf[pvm + 8 + (lane >> 2)];
      float fA1 = fbuf[pvm + 16 + (lane >> 2)];
      float fB1 = fbuf[pvm + 24 + (lane >> 2)];
      bool need = (fA0 != 1.f) || (fB0 != 1.f) || (fA1 != 1.f) || (fB1 != 1.f);
      if (__any_sync(0xffffffffu, need)){
        #pragma unroll
        for (int nt = 0; nt < 16; nt++){
          accY[0][nt][0] *= fA0; accY[0][nt][1] *= fA0;
          accY[0][nt][2] *= fB0; accY[0][nt][3] *= fB0;
          accY[1][nt][0] *= fA1; accY[1][nt][1] *= fA1;
          accY[1][nt][2] *= fB1; accY[1][nt][3] *= fB1;
        }
      }
    }

    const uint32_t Vbase = sb + SM_VR + (j & 1)*32768;
    const uint32_t Kbase = sb + SM_KR + ((j + 1) & 1)*32768;
    const bool do_s = (j + 1 < NCH);

    #pragma unroll
    for (int nt = 0; nt < 8; nt++){
      accS[nt][0] = 0.f; accS[nt][1] = 0.f; accS[nt][2] = 0.f; accS[nt][3] = 0.f;
    }

    // ---- interleaved: PV_j (32 rows x 128 dims) + S_{j+1} -------------------
    #pragma unroll
    for (int u = 0; u < 4; u++){
      {
        const int cA = u*2 + csel;
        uint32_t pa[2][4];
        #pragma unroll
        for (int mt = 0; mt < 2; mt++){
          int prow = pvm + mt*16 + rsel;
          uint32_t ad = sb + SM_P + prow*128 + ((cA ^ (prow & 7)) << 4);
          ldm4(pa[mt][0], pa[mt][1], pa[mt][2], pa[mt][3], ad);
        }
        #pragma unroll
        for (int g = 0; g < 8; g++){
          int vrow = pvd + g*16 + rsel;
          uint32_t bd = Vbase + vrow*128 + ((cA ^ (vrow & 7)) << 4);
          uint32_t r0, r1, r2, r3;
          ldm4(r0, r1, r2, r3, bd);
          uint32_t be[2] = {r0, r2}, bo[2] = {r1, r3};
          #pragma unroll
          for (int mt = 0; mt < 2; mt++){
            mma16816(accY[mt][2*g],   pa[mt], be);
            mma16816(accY[mt][2*g+1], pa[mt], bo);
          }
        }
      }
      if (do_s){
        #pragma unroll
        for (int s = 0; s < 4; s++){
          const int cA = (u*4 + s)*2 + csel;
          int qrow = qs + rsel;
          uint32_t ad = sb + SM_Q + qrow*512 + ((cA ^ (qrow & 7)) << 4);
          uint32_t qh[4];
          ldm4(qh[0], qh[1], qh[2], qh[3], ad);
          #pragma unroll
          for (int g = 0; g < 4; g++){
            int krow = g*16 + rsel;
            uint32_t bd = Kbase + krow*512 + ((cA ^ (krow & 7)) << 4);
            uint32_t r0, r1, r2, r3;
            ldm4(r0, r1, r2, r3, bd);
            uint32_t be[2] = {r0, r2}, bo[2] = {r1, r3};
            mma16816(accS[2*g],   qh, be);
            mma16816(accS[2*g+1], qh, bo);
          }
        }
      }
    }
  }

  cp_wait0();
  // ---- publish l, then normalize + store ------------------------------------
  if ((lane & 3) == 0){
    fbuf[qs + (lane >> 2)]     = l0r;
    fbuf[qs + 8 + (lane >> 2)] = l1r;
  }
  __syncthreads();

  float* stg = (float*)sm;                     // [128 tokens][260]
  {
    float iA0 = 1.0f / fbuf[pvm + (lane >> 2)];
    float iB0 = 1.0f / fbuf[pvm + 8 + (lane >> 2)];
    float iA1 = 1.0f / fbuf[pvm + 16 + (lane >> 2)];
    float iB1 = 1.0f / fbuf[pvm + 24 + (lane >> 2)];
    int rA0 = pvm + (lane >> 2);
    #pragma unroll
    for (int nt = 0; nt < 16; nt++){
      int c = pvd + nt*8 + (lane & 3)*2;
      stg[rA0*260 + c]        = accY[0][nt][0]*iA0;
      stg[rA0*260 + c + 1]    = accY[0][nt][1]*iA0;
      stg[(rA0+8)*260 + c]    = accY[0][nt][2]*iB0;
      stg[(rA0+8)*260 + c + 1]= accY[0][nt][3]*iB0;
      stg[(rA0+16)*260 + c]     = accY[1][nt][0]*iA1;
      stg[(rA0+16)*260 + c + 1] = accY[1][nt][1]*iA1;
      stg[(rA0+24)*260 + c]     = accY[1][nt][2]*iB1;
      stg[(rA0+24)*260 + c + 1] = accY[1][nt][3]*iB1;
    }
  }
  __syncthreads();
  #pragma unroll
  for (int it = 0; it < 4; it++){
    int dim = it*64 + (tid >> 2);
    int seg = (tid & 3) * 32;
    float* op = out + (size_t)(b*CC + dim)*NN + q0 + seg;
    #pragma unroll
    for (int k = 0; k < 32; k += 4){
      float4 v;
      v.x = stg[(seg + k + 0)*260 + dim];
      v.y = stg[(seg + k + 1)*260 + dim];
      v.z = stg[(seg + k + 2)*260 + dim];
      v.w = stg[(seg + k + 3)*260 + dim];
      *(float4*)(op + k) = v;
    }
  }
}

// ---------------- launch ----------------------------------------------------
extern "C" void kernel_launch(void* const* d_in, const int* in_sizes, int n_in,
                              void* d_out, int out_size)
{
    const float* x  = (const float*)d_in[0];
    const float* wq = (const float*)d_in[1];
    const float* wk = (const float*)d_in[2];
    const float* wv = (const float*)d_in[3];
    float* out = (float*)d_out;

    __half *X, *Pt, *Wv, *T, *Vt;
    cudaGetSymbolAddress((void**)&X,  g_X);
    cudaGetSymbolAddress((void**)&Pt, g_Pt);  cudaGetSymbolAddress((void**)&Wv, g_Wv);
    cudaGetSymbolAddress((void**)&T,  g_T);   cudaGetSymbolAddress((void**)&Vt, g_Vt);

    // 69632 >= max(2*32768 staging, 128*133*4 = 68096 transpose stage)
    const int SMEM_P = 69632;
    cudaFuncSetAttribute((const void*)gemm_mma<0>,
        cudaFuncAttributeMaxDynamicSharedMemorySize, SMEM_P);
    cudaFuncSetAttribute((const void*)gemm_mma<1>,
        cudaFuncAttributeMaxDynamicSharedMemorySize, SMEM_P);
    cudaFuncSetAttribute((const void*)flash_kernel,
        cudaFuncAttributeMaxDynamicSharedMemorySize, SM_FLASH);

    // 1) X = x + PE, fp16, (B,N,C)
    pe_transpose_kernel<<<dim3(NN/32, CC/32, BB), dim3(32,32)>>>(x);

    // 2) Pt = (0.0625*log2e) * Wq^T Wk  |  Wv -> fp16 (merged)
    prep_kernel<<<2*CC, CC>>>(wq, wk, wv);

    // 3) T = X @ Pt^T -> fp16 row-major
    gemm_mma<0><<<dim3(CC/128, MT/128, 1), 256, SMEM_P>>>(X, Pt, T, CC, CC, CC);

    // 4) Vt = (X @ Wv^T)^T -> fp16 (B,C,N), coalesced + conflict-free staging
    gemm_mma<1><<<dim3(CC/128, MT/128, 1), 256, SMEM_P>>>(X, Wv, Vt, CC, CC, CC);

    // 5) fused flash attention -> writes out (B,C,H,W) directly
    flash_kernel<<<dim3(NN/BQ, BB), 256, SM_FLASH>>>(out);
}